// round 15
// baseline (speedup 1.0000x reference)
#include <cuda_runtime.h>
#include <cuda_fp16.h>
#include <cstdint>
#include <math.h>

// Problem constants
#define BB   4
#define TT   4096
#define HH   8
#define LDIM 128
#define FFND 512
#define DD   1024
#define TOK  (BB*TT)
#define TED  2048

// Shared GEMM constants (round-9 champion inner loop for G3)
#define BM 128
#define BN 128
#define BKC 32
#define STAGES 4
#define ASTR 40
#define BSTR 136
#define A_ST (BM*ASTR)
#define B_ST (BKC*BSTR)
#define SMEM_BYTES (STAGES*(A_ST+B_ST)*2)   // 75776 B -> 2 CTAs/SM

// Fused G1+G2 kernel layout (halves)
#define FTHREADS 512
#define FX_STR 136
#define FX_OFF 0                      // x tile: 128 x 136
#define FH_OFF (128*FX_STR)           // h1 buf: 128 x 136
#define FW_OFF (2*128*FX_STR)         // W ring: 4 x (32 x 136)
#define F_SMEM ((2*128*FX_STR + STAGES*B_ST)*2)   // 104448 B -> 1 CTA/SM

// Scratch
__device__ float  g_ss[BB * 2 * DD];
__device__ float  g_y [(long)TOK * DD];
__device__ __half g_g [(long)TOK * DD];
__device__ __half g_w1h[HH * LDIM * FFND];
__device__ __half g_w2h[HH * FFND * LDIM];
__device__ __half g_owh[DD * DD];

__device__ __forceinline__ float silu_f(float v) { return v / (1.0f + expf(-v)); }
__device__ __forceinline__ float gelu_f(float v) { return 0.5f * v * (1.0f + erff(v * 0.70710678118654752f)); }
__device__ __forceinline__ uint32_t h2u(__half2 h) {
    union { __half2 h; uint32_t u; } cvt;
    cvt.h = h;
    return cvt.u;
}
static __device__ __forceinline__ uint32_t smem_u32(const void* p) {
    uint32_t a;
    asm("{ .reg .u64 t; cvta.to.shared.u64 t, %1; cvt.u32.u64 %0, t; }" : "=r"(a) : "l"(p));
    return a;
}
__device__ __forceinline__ void cp_async16(uint32_t dst, const void* src) {
    asm volatile("cp.async.cg.shared.global [%0], [%1], 16;" :: "r"(dst), "l"(src));
}
#define CP_COMMIT() asm volatile("cp.async.commit_group;" ::: "memory")
#define CP_WAIT2()  asm volatile("cp.async.wait_group 2;" ::: "memory")

// ---------------------------------------------------------------------------
// f32 -> f16 conversion for the three weight tensors (12 MB)
// ---------------------------------------------------------------------------
#define N4_W1 ((long)HH * LDIM * FFND / 4)
#define N4_W2 ((long)HH * FFND * LDIM / 4)
#define N4_OW ((long)DD * DD / 4)
#define N4_W  (N4_W1 + N4_W2 + N4_OW)

__global__ __launch_bounds__(256) void to_half_w(
    const float4* __restrict__ w1, uint2* __restrict__ w1o,
    const float4* __restrict__ w2, uint2* __restrict__ w2o,
    const float4* __restrict__ ow, uint2* __restrict__ owo)
{
    long i = (long)blockIdx.x * 256 + threadIdx.x;
    if (i >= N4_W) return;
    const float4* in; uint2* out; long off;
    if (i < N4_W1)             { in = w1; out = w1o; off = i; }
    else if (i < N4_W1 + N4_W2){ in = w2; out = w2o; off = i - N4_W1; }
    else                       { in = ow; out = owo; off = i - N4_W1 - N4_W2; }
    float4 v = in[off];
    uint2 o;
    o.x = h2u(__floats2half2_rn(v.x, v.y));
    o.y = h2u(__floats2half2_rn(v.z, v.w));
    out[off] = o;
}

// ---------------------------------------------------------------------------
// Fused G1+G2: per (token-block by, head bz):
//   h1 = gelu(x_tile @ W1 + b1) computed 128-col chunk at a time into SMEM,
//   y  = h1 @ W2 + b2 accumulated in registers, written fp32 to yv.
// 512 threads, 16 warps = 4(m) x 4(n), warp tile 32x32. h1 NEVER touches DRAM.
// W1/W2 chunks stream through one continuous 4-stage cp.async ring.
// Accumulation order identical to the split kernels (bit-identical result).
// ---------------------------------------------------------------------------
__global__ void __launch_bounds__(FTHREADS, 1) fused_mlp(
    const float* __restrict__ X,     // x fp32
    const __half* __restrict__ W1,   // w1h (H,128,512)
    const __half* __restrict__ W2,   // w2h (H,512,128)
    const float* __restrict__ B1,    // b1 (H,512)
    const float* __restrict__ B2,    // b2 (H,128)
    float* __restrict__ Y)           // yv (TOK, DD)
{
    extern __shared__ __half sm[];
    const uint32_t sBase = smem_u32(sm);
    const uint32_t sX = sBase + FX_OFF * 2;
    const uint32_t sH = sBase + FH_OFF * 2;
    const uint32_t sW = sBase + FW_OFF * 2;

    const int tid  = threadIdx.x;
    const int lane = tid & 31, wid = tid >> 5;
    const int wm   = wid >> 2, wn = wid & 3;     // 4 x 4 warps
    const int gid  = lane >> 2, tig = lane & 3;
    const int by = blockIdx.x, bz = blockIdx.y;

    const float*  Xp  = X  + 128 * bz + (long)(by * 128) * DD;
    const __half* W1p = W1 + (long)bz * LDIM * FFND;
    const __half* W2p = W2 + (long)bz * FFND * LDIM;

    // W-chunk ring: q = bx*8 + phase*4 + c. phase 0 = W1, phase 1 = W2.
    const int bk = tid >> 4;            // k-row 0..31
    const int bgrp = tid & 15;          // 16B group within 128-half row
    auto issueW = [&](int q, int s) {
        const int bx = q >> 3, ph = (q >> 2) & 1, c = q & 3;
        const __half* src = ph == 0
            ? W1p + (long)(c * 32 + bk) * FFND + bx * 128
            : W2p + (long)(bx * 128 + c * 32 + bk) * LDIM;
        const uint32_t dst = sW + (uint32_t)(s * B_ST + bk * BSTR) * 2 + bgrp * 16;
        cp_async16(dst, src + bgrp * 8);
    };
    issueW(0, 0); CP_COMMIT();
    issueW(1, 1); CP_COMMIT();
    issueW(2, 2); CP_COMMIT();

    // x tile: fp32 -> fp16, resident (overlaps the prologue cp.asyncs)
    #pragma unroll 2
    for (int it = 0; it < 8; it++) {
        const int idx = it * FTHREADS + tid;   // 0..4095
        const int row = idx >> 5;
        const int c4  = idx & 31;
        float4 v = *(const float4*)(Xp + (long)row * DD + c4 * 4);
        uint2 o;
        o.x = h2u(__floats2half2_rn(v.x, v.y));
        o.y = h2u(__floats2half2_rn(v.z, v.w));
        *(uint2*)(sm + row * FX_STR + c4 * 4) = o;
    }

    // fragment lane bases
    const int a_row = wm * 32 + (lane & 15);   // + i*16
    const int a_sub = (lane >> 4) << 3;        // + k base
    const int b_row = lane & 15;
    const int b_col = wn * 32;

    float yacc[2][4][4];
    #pragma unroll
    for (int i = 0; i < 2; i++)
        #pragma unroll
        for (int j = 0; j < 4; j++)
            #pragma unroll
            for (int e = 0; e < 4; e++) yacc[i][j][e] = 0.0f;

    float hacc[2][4][4];

    for (int q = 0; q < 32; q++) {
        const int bx = q >> 3, ph = (q >> 2) & 1, c = q & 3;
        CP_WAIT2();
        __syncthreads();                // chunk q ready; also orders sX/sH stores
        if (q + 3 < 32) issueW(q + 3, (q + 3) & 3);
        CP_COMMIT();

        if (ph == 0 && c == 0) {
            #pragma unroll
            for (int i = 0; i < 2; i++)
                #pragma unroll
                for (int j = 0; j < 4; j++)
                    #pragma unroll
                    for (int e = 0; e < 4; e++) hacc[i][j][e] = 0.0f;
        }

        const uint32_t wS = sW + (uint32_t)((q & 3) * B_ST) * 2;
        const uint32_t aS = ph == 0 ? sX : sH;
        const int acol0 = ph == 0 ? bx * 32 + c * 0 : 0;  // see below
        #pragma unroll
        for (int ks = 0; ks < 2; ks++) {
            // GEMM1: A = x, k = c*32 + ks*16 (within the head's 128)
            // GEMM2: A = h1buf, k = c*32 + ks*16 (within this bx's 128)
            const int akb = c * 32 + ks * 16;
            const int bkb = ks * 16;
            uint32_t af[2][4], bf[4][2];
            #pragma unroll
            for (int i = 0; i < 2; i++) {
                const uint32_t addr = aS + (uint32_t)((a_row + i * 16) * FX_STR + akb + a_sub) * 2;
                asm volatile("ldmatrix.sync.aligned.m8n8.x4.shared.b16 {%0,%1,%2,%3}, [%4];"
                             : "=r"(af[i][0]), "=r"(af[i][1]), "=r"(af[i][2]), "=r"(af[i][3])
                             : "r"(addr));
            }
            #pragma unroll
            for (int j = 0; j < 4; j++) {
                const uint32_t addr = wS + (uint32_t)((bkb + b_row) * BSTR + b_col + j * 8) * 2;
                asm volatile("ldmatrix.sync.aligned.m8n8.x2.trans.shared.b16 {%0,%1}, [%2];"
                             : "=r"(bf[j][0]), "=r"(bf[j][1]) : "r"(addr));
            }
            if (ph == 0) {
                #pragma unroll
                for (int i = 0; i < 2; i++)
                    #pragma unroll
                    for (int j = 0; j < 4; j++)
                        asm volatile(
                            "mma.sync.aligned.m16n8k16.row.col.f32.f16.f16.f32 "
                            "{%0,%1,%2,%3}, {%4,%5,%6,%7}, {%8,%9}, {%0,%1,%2,%3};"
                            : "+f"(hacc[i][j][0]), "+f"(hacc[i][j][1]),
                              "+f"(hacc[i][j][2]), "+f"(hacc[i][j][3])
                            : "r"(af[i][0]), "r"(af[i][1]), "r"(af[i][2]), "r"(af[i][3]),
                              "r"(bf[j][0]), "r"(bf[j][1]));
            } else {
                #pragma unroll
                for (int i = 0; i < 2; i++)
                    #pragma unroll
                    for (int j = 0; j < 4; j++)
                        asm volatile(
                            "mma.sync.aligned.m16n8k16.row.col.f32.f16.f16.f32 "
                            "{%0,%1,%2,%3}, {%4,%5,%6,%7}, {%8,%9}, {%0,%1,%2,%3};"
                            : "+f"(yacc[i][j][0]), "+f"(yacc[i][j][1]),
                              "+f"(yacc[i][j][2]), "+f"(yacc[i][j][3])
                            : "r"(af[i][0]), "r"(af[i][1]), "r"(af[i][2]), "r"(af[i][3]),
                              "r"(bf[j][0]), "r"(bf[j][1]));
            }
        }
        (void)acol0;

        if (ph == 0 && c == 3) {
            // h1 chunk complete: bias + gelu -> fp16 -> sH
            const float* bsp = B1 + bz * FFND + bx * 128;
            #pragma unroll
            for (int i = 0; i < 2; i++) {
                const int r0 = wm * 32 + i * 16 + gid;
                #pragma unroll
                for (int j = 0; j < 4; j++) {
                    const int cn = wn * 32 + j * 8 + tig * 2;
                    const float b0 = bsp[cn], b1v = bsp[cn + 1];
                    float v00 = gelu_f(hacc[i][j][0] + b0);
                    float v01 = gelu_f(hacc[i][j][1] + b1v);
                    float v10 = gelu_f(hacc[i][j][2] + b0);
                    float v11 = gelu_f(hacc[i][j][3] + b1v);
                    *(uint32_t*)(sm + FH_OFF + r0 * FX_STR + cn) =
                        h2u(__floats2half2_rn(v00, v01));
                    *(uint32_t*)(sm + FH_OFF + (r0 + 8) * FX_STR + cn) =
                        h2u(__floats2half2_rn(v10, v11));
                }
            }
            // next iteration's __syncthreads orders these stores before ldmatrix
        }
    }

    // ---- epilogue: y + b2 -> yv (fp32) ----
    const float* bsp = B2 + bz * LDIM;
    #pragma unroll
    for (int i = 0; i < 2; i++) {
        const int r0 = by * 128 + wm * 32 + i * 16 + gid;
        #pragma unroll
        for (int j = 0; j < 4; j++) {
            const int cn = wn * 32 + j * 8 + tig * 2;
            const float b0 = bsp[cn], b1v = bsp[cn + 1];
            float2 lo = { yacc[i][j][0] + b0, yacc[i][j][1] + b1v };
            float2 hi = { yacc[i][j][2] + b0, yacc[i][j][3] + b1v };
            float* Yp = Y + bz * 128;
            *(float2*)(Yp + (long)r0 * DD + cn)       = lo;
            *(float2*)(Yp + (long)(r0 + 8) * DD + cn) = hi;
        }
    }
}

// ---------------------------------------------------------------------------
// fp16 mma.sync m16n8k16 GEMM (round-9 champion), used for G3.
// EPI 2 = bias + residual -> float
// ---------------------------------------------------------------------------
__global__ void __launch_bounds__(256, 2) mma_gemm_out(
    const __half* __restrict__ A, int lda,
    const __half* __restrict__ B, int ldb,
    float* __restrict__ C, int ldc,
    const float* __restrict__ bias,
    const float* __restrict__ extra, int K)
{
    extern __shared__ __half sm[];
    const uint32_t sA = smem_u32(sm);
    const uint32_t sB = sA + STAGES * A_ST * 2;

    const int tid  = threadIdx.x;
    const int lane = tid & 31, wid = tid >> 5;
    const int wm   = wid >> 2, wn = wid & 3;
    const int gid  = lane >> 2, tig = lane & 3;
    const int bx = blockIdx.x, by = blockIdx.y;
    const int nC = K / BKC;

    const __half* Ap = A + (long)(by * BM) * lda;
    const __half* Bp = B + bx * BN;

    const int ar = tid >> 1, ac0 = (tid & 1) * 2;
    const int bk = tid >> 3, bc0 = (tid & 7) * 2;

    float acc[4][4][4];
    #pragma unroll
    for (int i = 0; i < 4; i++)
        #pragma unroll
        for (int j = 0; j < 4; j++)
            #pragma unroll
            for (int e = 0; e < 4; e++) acc[i][j][e] = 0.0f;

    auto issue = [&](int c, int s) {
        const __half* a_src = Ap + (long)ar * lda + c * BKC;
        const uint32_t a_dst = sA + (uint32_t)(s * A_ST + ar * ASTR) * 2;
        #pragma unroll
        for (int p = 0; p < 2; p++)
            cp_async16(a_dst + (ac0 + p) * 16, a_src + (ac0 + p) * 8);
        const __half* b_src = Bp + (long)(c * BKC + bk) * ldb;
        const uint32_t b_dst = sB + (uint32_t)(s * B_ST + bk * BSTR) * 2;
        #pragma unroll
        for (int p = 0; p < 2; p++)
            cp_async16(b_dst + (bc0 + p) * 16, b_src + (bc0 + p) * 8);
    };

    #pragma unroll
    for (int s = 0; s < STAGES - 1; s++) {
        if (s < nC) issue(s, s);
        CP_COMMIT();
    }

    const int a_row = wm * 64 + (lane & 15);
    const int a_col = (lane >> 4) << 3;
    const int b_row = lane & 15;
    const int b_col = wn * 32;

    for (int c = 0; c < nC; c++) {
        CP_WAIT2();
        __syncthreads();
        const int nxt = c + STAGES - 1;
        if (nxt < nC) issue(nxt, nxt & (STAGES - 1));
        CP_COMMIT();

        const uint32_t aS = sA + (uint32_t)((c & (STAGES - 1)) * A_ST) * 2;
        const uint32_t bS = sB + (uint32_t)((c & (STAGES - 1)) * B_ST) * 2;
        #pragma unroll
        for (int ks = 0; ks < 2; ks++) {
            const int kb = ks * 16;
            uint32_t af[4][4], bf[4][2];
            #pragma unroll
            for (int i = 0; i < 4; i++) {
                const uint32_t addr = aS + (uint32_t)((a_row + i * 16) * ASTR + kb + a_col) * 2;
                asm volatile("ldmatrix.sync.aligned.m8n8.x4.shared.b16 {%0,%1,%2,%3}, [%4];"
                             : "=r"(af[i][0]), "=r"(af[i][1]), "=r"(af[i][2]), "=r"(af[i][3])
                             : "r"(addr));
            }
            #pragma unroll
            for (int j = 0; j < 4; j++) {
                const uint32_t addr = bS + (uint32_t)((kb + b_row) * BSTR + b_col + j * 8) * 2;
                asm volatile("ldmatrix.sync.aligned.m8n8.x2.trans.shared.b16 {%0,%1}, [%2];"
                             : "=r"(bf[j][0]), "=r"(bf[j][1]) : "r"(addr));
            }
            #pragma unroll
            for (int i = 0; i < 4; i++)
                #pragma unroll
                for (int j = 0; j < 4; j++)
                    asm volatile(
                        "mma.sync.aligned.m16n8k16.row.col.f32.f16.f16.f32 "
                        "{%0,%1,%2,%3}, {%4,%5,%6,%7}, {%8,%9}, {%0,%1,%2,%3};"
                        : "+f"(acc[i][j][0]), "+f"(acc[i][j][1]),
                          "+f"(acc[i][j][2]), "+f"(acc[i][j][3])
                        : "r"(af[i][0]), "r"(af[i][1]), "r"(af[i][2]), "r"(af[i][3]),
                          "r"(bf[j][0]), "r"(bf[j][1]));
        }
    }

    #pragma unroll
    for (int i = 0; i < 4; i++) {
        const int r0 = by * BM + wm * 64 + i * 16 + gid;
        #pragma unroll
        for (int j = 0; j < 4; j++) {
            const int cn = bx * BN + wn * 32 + j * 8 + tig * 2;
            const float b0 = bias[cn], b1 = bias[cn + 1];
            float v00 = acc[i][j][0] + b0 + extra[(long)r0 * ldc + cn];
            float v01 = acc[i][j][1] + b1 + extra[(long)r0 * ldc + cn + 1];
            float v10 = acc[i][j][2] + b0 + extra[(long)(r0 + 8) * ldc + cn];
            float v11 = acc[i][j][3] + b1 + extra[(long)(r0 + 8) * ldc + cn + 1];
            float2 lo = { v00, v01 }, hi = { v10, v11 };
            *(float2*)(C + (long)r0 * ldc + cn)       = lo;
            *(float2*)(C + (long)(r0 + 8) * ldc + cn) = hi;
        }
    }
}

// ---------------------------------------------------------------------------
// emb: ss[b,:] = silu(emb[b,:]) @ emb_W + emb_b
// ---------------------------------------------------------------------------
__global__ __launch_bounds__(256) void emb_kernel(
    const float* __restrict__ emb, const float* __restrict__ embW,
    const float* __restrict__ embb, float* __restrict__ ss)
{
    __shared__ float se[TED];
    const int b = blockIdx.y;
    const int j = blockIdx.x * 256 + threadIdx.x;
    for (int i = threadIdx.x; i < TED; i += 256)
        se[i] = silu_f(emb[b * TED + i]);
    __syncthreads();
    float acc = embb[j];
    #pragma unroll 8
    for (int k = 0; k < TED; k++)
        acc += se[k] * embW[(long)k * TED + j];
    ss[b * TED + j] = acc;
}

// ---------------------------------------------------------------------------
// per-token LayerNorm -> modulate -> SiLU -> fp16. Warp-per-token.
// ---------------------------------------------------------------------------
__global__ __launch_bounds__(256) void ln_mod_silu(
    const float* __restrict__ y, const float* __restrict__ ss,
    const float* __restrict__ lnw, const float* __restrict__ lnb,
    __half* __restrict__ g)
{
    const int warp = threadIdx.x >> 5, lane = threadIdx.x & 31;
    const long t = (long)blockIdx.x * 8 + warp;
    const float* yp = y + t * DD;

    float4 v[8];
    float s = 0.f, q = 0.f;
    #pragma unroll
    for (int i = 0; i < 8; i++) {
        v[i] = *(const float4*)(yp + i * 128 + lane * 4);
        s += v[i].x + v[i].y + v[i].z + v[i].w;
        q += v[i].x * v[i].x + v[i].y * v[i].y + v[i].z * v[i].z + v[i].w * v[i].w;
    }
    #pragma unroll
    for (int o = 16; o; o >>= 1) {
        s += __shfl_xor_sync(0xffffffffu, s, o);
        q += __shfl_xor_sync(0xffffffffu, q, o);
    }
    const float mean = s * (1.0f / DD);
    const float rstd = rsqrtf(q * (1.0f / DD) - mean * mean + 1e-5f);

    const int b = (int)(t >> 12);
    const float* scp = ss + b * TED;
    __half* gp = g + t * DD;
    #pragma unroll
    for (int i = 0; i < 8; i++) {
        const int c = i * 128 + lane * 4;
        float4 sc = *(const float4*)(scp + c);
        float4 sh = *(const float4*)(scp + DD + c);
        float4 w4 = *(const float4*)(lnw + c);
        float4 b4 = *(const float4*)(lnb + c);
        float o0, o1, o2, o3, h;
        h = (v[i].x - mean) * rstd * w4.x + b4.x; h = h * (1.f + sc.x) + sh.x; o0 = silu_f(h);
        h = (v[i].y - mean) * rstd * w4.y + b4.y; h = h * (1.f + sc.y) + sh.y; o1 = silu_f(h);
        h = (v[i].z - mean) * rstd * w4.z + b4.z; h = h * (1.f + sc.z) + sh.z; o2 = silu_f(h);
        h = (v[i].w - mean) * rstd * w4.w + b4.w; h = h * (1.f + sc.w) + sh.w; o3 = silu_f(h);
        uint2 o;
        o.x = h2u(__floats2half2_rn(o0, o1));
        o.y = h2u(__floats2half2_rn(o2, o3));
        *(uint2*)(gp + c) = o;
    }
}

// ---------------------------------------------------------------------------
extern "C" void kernel_launch(void* const* d_in, const int* in_sizes, int n_in,
                              void* d_out, int out_size)
{
    const float* x     = (const float*)d_in[0];
    const float* emb   = (const float*)d_in[1];
    const float* W1    = (const float*)d_in[2];
    const float* b1    = (const float*)d_in[3];
    const float* W2    = (const float*)d_in[4];
    const float* b2    = (const float*)d_in[5];
    const float* ln_w  = (const float*)d_in[6];
    const float* ln_b  = (const float*)d_in[7];
    const float* emb_W = (const float*)d_in[8];
    const float* emb_b = (const float*)d_in[9];
    const float* out_W = (const float*)d_in[10];
    const float* out_b = (const float*)d_in[11];
    float* out = (float*)d_out;

    float *ss, *yv;
    __half *gg, *w1h, *w2h, *owh;
    cudaGetSymbolAddress((void**)&ss, g_ss);
    cudaGetSymbolAddress((void**)&yv, g_y);
    cudaGetSymbolAddress((void**)&gg, g_g);
    cudaGetSymbolAddress((void**)&w1h, g_w1h);
    cudaGetSymbolAddress((void**)&w2h, g_w2h);
    cudaGetSymbolAddress((void**)&owh, g_owh);

    cudaFuncSetAttribute(reinterpret_cast<const void*>(&fused_mlp),
                         cudaFuncAttributeMaxDynamicSharedMemorySize, F_SMEM);
    cudaFuncSetAttribute(reinterpret_cast<const void*>(&mma_gemm_out),
                         cudaFuncAttributeMaxDynamicSharedMemorySize, SMEM_BYTES);

    // 0) convert weights to fp16
    {
        long blocks = (N4_W + 255) / 256;
        to_half_w<<<(int)blocks, 256>>>(
            (const float4*)W1, (uint2*)w1h,
            (const float4*)W2, (uint2*)w2h,
            (const float4*)out_W, (uint2*)owh);
    }

    // 1) scale/shift
    emb_kernel<<<dim3(8, 4), 256>>>(emb, emb_W, emb_b, ss);

    // 2+3) fused per-head MLP: yv = (gelu(x@W1+b1))@W2 + b2, h1 stays in SMEM
    fused_mlp<<<dim3(128, 8), FTHREADS, F_SMEM>>>(x, w1h, w2h, b1, b2, yv);

    // 4) g = half(silu(modulated LN(y)))
    ln_mod_silu<<<TOK / 8, 256>>>(yv, ss, ln_w, ln_b, gg);

    // 5) out = x + g @ out_W + out_b: M=16384, N=1024, K=1024
    mma_gemm_out<<<dim3(8, 128), 256, SMEM_BYTES>>>(
        gg, DD,
        owh, DD,
        out, DD,
        out_b, x, DD);
}

// round 17
// speedup vs baseline: 1.0618x; 1.0618x over previous
#include <cuda_runtime.h>
#include <cuda_fp16.h>
#include <cstdint>
#include <math.h>

// Problem constants
#define BB   4
#define TT   4096
#define HH   8
#define LDIM 128
#define FFND 512
#define DD   1024
#define TOK  (BB*TT)
#define TED  2048

// GEMM tiling (fp16 operands) — round-9 champion config
#define BM 128
#define BN 128
#define BKC 32
#define STAGES 4
#define ASTR 40        // halves per A row (80B, conflict-free ldmatrix)
#define BSTR 136       // halves per B row (272B, conflict-free ldmatrix)
#define A_ST (BM*ASTR)
#define B_ST (BKC*BSTR)
#define SMEM_BYTES (STAGES*(A_ST+B_ST)*2)   // 75776 B -> 2 CTAs/SM

// G1 specialization: A resident (128x128, padded rows), B-only 4-stage pipeline
#define G1_ASTR 136
#define G1_A_HALVES (128*G1_ASTR)
#define G1_SMEM ((G1_A_HALVES + STAGES*B_ST)*2) // 69632 B -> 2 CTAs/SM

// Scratch
__device__ float  g_ss[BB * 2 * DD];
__device__ __half g_h1[(long)TOK * HH * FFND];
__device__ __half g_yh[(long)TOK * DD];          // y now fp16
__device__ __half g_g [(long)TOK * DD];
__device__ __half g_w1h[HH * LDIM * FFND];
__device__ __half g_w2h[HH * FFND * LDIM];
__device__ __half g_owh[DD * DD];

__device__ __forceinline__ float silu_f(float v) { return v / (1.0f + expf(-v)); }
__device__ __forceinline__ float gelu_f(float v) { return 0.5f * v * (1.0f + erff(v * 0.70710678118654752f)); }
__device__ __forceinline__ uint32_t h2u(__half2 h) {
    union { __half2 h; uint32_t u; } cvt;
    cvt.h = h;
    return cvt.u;
}
__device__ __forceinline__ __half2 u2h(uint32_t u) {
    union { uint32_t u; __half2 h; } cvt;
    cvt.u = u;
    return cvt.h;
}
static __device__ __forceinline__ uint32_t smem_u32(const void* p) {
    uint32_t a;
    asm("{ .reg .u64 t; cvta.to.shared.u64 t, %1; cvt.u32.u64 %0, t; }" : "=r"(a) : "l"(p));
    return a;
}
__device__ __forceinline__ void cp_async16(uint32_t dst, const void* src) {
    asm volatile("cp.async.cg.shared.global [%0], [%1], 16;" :: "r"(dst), "l"(src));
}
#define CP_COMMIT() asm volatile("cp.async.commit_group;" ::: "memory")
#define CP_WAIT2()  asm volatile("cp.async.wait_group 2;" ::: "memory")

// ---------------------------------------------------------------------------
// f32 -> f16 conversion for the three weight tensors (12 MB)
// ---------------------------------------------------------------------------
#define N4_W1 ((long)HH * LDIM * FFND / 4)
#define N4_W2 ((long)HH * FFND * LDIM / 4)
#define N4_OW ((long)DD * DD / 4)
#define N4_W  (N4_W1 + N4_W2 + N4_OW)

__global__ __launch_bounds__(256) void to_half_w(
    const float4* __restrict__ w1, uint2* __restrict__ w1o,
    const float4* __restrict__ w2, uint2* __restrict__ w2o,
    const float4* __restrict__ ow, uint2* __restrict__ owo)
{
    long i = (long)blockIdx.x * 256 + threadIdx.x;
    if (i >= N4_W) return;
    const float4* in; uint2* out; long off;
    if (i < N4_W1)             { in = w1; out = w1o; off = i; }
    else if (i < N4_W1 + N4_W2){ in = w2; out = w2o; off = i - N4_W1; }
    else                       { in = ow; out = owo; off = i - N4_W1 - N4_W2; }
    float4 v = in[off];
    uint2 o;
    o.x = h2u(__floats2half2_rn(v.x, v.y));
    o.y = h2u(__floats2half2_rn(v.z, v.w));
    out[off] = o;
}

// ---------------------------------------------------------------------------
// G1 specialized: h1 = half(gelu(x_head @ W1 + b1)), x read as FP32 and
// converted inline during the one-time A-tile load. (round-14 champion)
// ---------------------------------------------------------------------------
__global__ void __launch_bounds__(256, 2) g1_gemm(
    const float* __restrict__ A,    // x (fp32)
    const __half* __restrict__ B,   // w1h
    __half* __restrict__ C,         // h1
    const float* __restrict__ bias) // b1
{
    extern __shared__ __half sm[];
    const uint32_t sA = smem_u32(sm);            // [128][G1_ASTR]
    const uint32_t sB = sA + G1_A_HALVES * 2;    // [STAGES][BKC][BSTR]

    const int tid  = threadIdx.x;
    const int lane = tid & 31, wid = tid >> 5;
    const int wm   = wid >> 2, wn = wid & 3;
    const int gid  = lane >> 2, tig = lane & 3;
    const int by = blockIdx.x, bz = blockIdx.y;

    const float*  Ap = A + 128 * bz + (long)(by * 128) * DD;
    const __half* Bp = B + (long)bz * LDIM * FFND;

    const int bk = tid >> 3, bc0 = (tid & 7) * 2;
    auto issueB = [&](int q, int s) {
        const int bx = q >> 2, c = q & 3;
        const __half* b_src = Bp + (long)(c * BKC + bk) * FFND + bx * 128;
        const uint32_t b_dst = sB + (uint32_t)(s * B_ST + bk * BSTR) * 2;
        #pragma unroll
        for (int p = 0; p < 2; p++)
            cp_async16(b_dst + (bc0 + p) * 16, b_src + (bc0 + p) * 8);
    };
    issueB(0, 0); CP_COMMIT();
    issueB(1, 1); CP_COMMIT();
    issueB(2, 2); CP_COMMIT();

    #pragma unroll 4
    for (int it = 0; it < 16; it++) {
        const int idx = it * 256 + tid;
        const int row = idx >> 5;
        const int c4  = idx & 31;
        float4 v = *(const float4*)(Ap + (long)row * DD + c4 * 4);
        uint2 o;
        o.x = h2u(__floats2half2_rn(v.x, v.y));
        o.y = h2u(__floats2half2_rn(v.z, v.w));
        *(uint2*)(sm + row * G1_ASTR + c4 * 4) = o;
    }

    const int a_row = wm * 64 + (lane & 15);
    const int a_col = (lane >> 4) << 3;
    const int b_row = lane & 15;
    const int b_col = wn * 32;

    float acc[4][4][4];

    for (int q = 0; q < 16; q++) {
        const int c = q & 3, bx = q >> 2;
        CP_WAIT2();
        __syncthreads();
        if (q + 3 < 16) issueB(q + 3, (q + 3) & 3);
        CP_COMMIT();

        if (c == 0) {
            #pragma unroll
            for (int i = 0; i < 4; i++)
                #pragma unroll
                for (int j = 0; j < 4; j++)
                    #pragma unroll
                    for (int e = 0; e < 4; e++) acc[i][j][e] = 0.0f;
        }

        const uint32_t bS = sB + (uint32_t)((q & 3) * B_ST) * 2;
        #pragma unroll
        for (int ks = 0; ks < 2; ks++) {
            const int akb = c * 32 + ks * 16;
            const int bkb = ks * 16;
            uint32_t af[4][4], bf[4][2];
            #pragma unroll
            for (int i = 0; i < 4; i++) {
                const uint32_t addr = sA + (uint32_t)((a_row + i * 16) * G1_ASTR + akb + a_col) * 2;
                asm volatile("ldmatrix.sync.aligned.m8n8.x4.shared.b16 {%0,%1,%2,%3}, [%4];"
                             : "=r"(af[i][0]), "=r"(af[i][1]), "=r"(af[i][2]), "=r"(af[i][3])
                             : "r"(addr));
            }
            #pragma unroll
            for (int j = 0; j < 4; j++) {
                const uint32_t addr = bS + (uint32_t)((bkb + b_row) * BSTR + b_col + j * 8) * 2;
                asm volatile("ldmatrix.sync.aligned.m8n8.x2.trans.shared.b16 {%0,%1}, [%2];"
                             : "=r"(bf[j][0]), "=r"(bf[j][1]) : "r"(addr));
            }
            #pragma unroll
            for (int i = 0; i < 4; i++)
                #pragma unroll
                for (int j = 0; j < 4; j++)
                    asm volatile(
                        "mma.sync.aligned.m16n8k16.row.col.f32.f16.f16.f32 "
                        "{%0,%1,%2,%3}, {%4,%5,%6,%7}, {%8,%9}, {%0,%1,%2,%3};"
                        : "+f"(acc[i][j][0]), "+f"(acc[i][j][1]),
                          "+f"(acc[i][j][2]), "+f"(acc[i][j][3])
                        : "r"(af[i][0]), "r"(af[i][1]), "r"(af[i][2]), "r"(af[i][3]),
                          "r"(bf[j][0]), "r"(bf[j][1]));
        }

        if (c == 3) {
            const float* bsp = bias + bz * FFND + bx * 128;
            #pragma unroll
            for (int i = 0; i < 4; i++) {
                const int r0 = by * 128 + wm * 64 + i * 16 + gid;
                #pragma unroll
                for (int j = 0; j < 4; j++) {
                    const int cn = wn * 32 + j * 8 + tig * 2;
                    const float b0 = bsp[cn], b1v = bsp[cn + 1];
                    float v00 = gelu_f(acc[i][j][0] + b0);
                    float v01 = gelu_f(acc[i][j][1] + b1v);
                    float v10 = gelu_f(acc[i][j][2] + b0);
                    float v11 = gelu_f(acc[i][j][3] + b1v);
                    __half* Cp = C + bz * FFND + bx * 128;
                    *(uint32_t*)(Cp + (long)r0 * (HH * FFND) + cn) =
                        h2u(__floats2half2_rn(v00, v01));
                    *(uint32_t*)(Cp + (long)(r0 + 8) * (HH * FFND) + cn) =
                        h2u(__floats2half2_rn(v10, v11));
                }
            }
        }
    }
}

// ---------------------------------------------------------------------------
// fp16 mma.sync m16n8k16 GEMM (round-9 champion), G2 and G3.
// EPI: 1 = bias -> HALF (y), 2 = bias+residual -> float (out)
// ---------------------------------------------------------------------------
template <int EPI, typename CT>
__global__ void __launch_bounds__(256, 2) mma_gemm(
    const __half* __restrict__ A, long aZ, int lda,
    const __half* __restrict__ B, long bZ, int ldb,
    CT* __restrict__ C, long cZ, int ldc,
    const float* __restrict__ bias, int biasZ,
    const float* __restrict__ extra, int K)
{
    extern __shared__ __half sm[];
    const uint32_t sA = smem_u32(sm);
    const uint32_t sB = sA + STAGES * A_ST * 2;

    const int tid  = threadIdx.x;
    const int lane = tid & 31, wid = tid >> 5;
    const int wm   = wid >> 2, wn = wid & 3;
    const int gid  = lane >> 2, tig = lane & 3;
    const int bx = blockIdx.x, by = blockIdx.y, bz = blockIdx.z;
    const int nC = K / BKC;

    const __half* Ap = A + aZ * bz + (long)(by * BM) * lda;
    const __half* Bp = B + bZ * bz + bx * BN;

    const int ar = tid >> 1, ac0 = (tid & 1) * 2;
    const int bk = tid >> 3, bc0 = (tid & 7) * 2;

    float acc[4][4][4];
    #pragma unroll
    for (int i = 0; i < 4; i++)
        #pragma unroll
        for (int j = 0; j < 4; j++)
            #pragma unroll
            for (int e = 0; e < 4; e++) acc[i][j][e] = 0.0f;

    auto issue = [&](int c, int s) {
        const __half* a_src = Ap + (long)ar * lda + c * BKC;
        const uint32_t a_dst = sA + (uint32_t)(s * A_ST + ar * ASTR) * 2;
        #pragma unroll
        for (int p = 0; p < 2; p++)
            cp_async16(a_dst + (ac0 + p) * 16, a_src + (ac0 + p) * 8);
        const __half* b_src = Bp + (long)(c * BKC + bk) * ldb;
        const uint32_t b_dst = sB + (uint32_t)(s * B_ST + bk * BSTR) * 2;
        #pragma unroll
        for (int p = 0; p < 2; p++)
            cp_async16(b_dst + (bc0 + p) * 16, b_src + (bc0 + p) * 8);
    };

    #pragma unroll
    for (int s = 0; s < STAGES - 1; s++) {
        if (s < nC) issue(s, s);
        CP_COMMIT();
    }

    const int a_row = wm * 64 + (lane & 15);
    const int a_col = (lane >> 4) << 3;
    const int b_row = lane & 15;
    const int b_col = wn * 32;

    for (int c = 0; c < nC; c++) {
        CP_WAIT2();
        __syncthreads();
        const int nxt = c + STAGES - 1;
        if (nxt < nC) issue(nxt, nxt & (STAGES - 1));
        CP_COMMIT();

        const uint32_t aS = sA + (uint32_t)((c & (STAGES - 1)) * A_ST) * 2;
        const uint32_t bS = sB + (uint32_t)((c & (STAGES - 1)) * B_ST) * 2;
        #pragma unroll
        for (int ks = 0; ks < 2; ks++) {
            const int kb = ks * 16;
            uint32_t af[4][4], bf[4][2];
            #pragma unroll
            for (int i = 0; i < 4; i++) {
                const uint32_t addr = aS + (uint32_t)((a_row + i * 16) * ASTR + kb + a_col) * 2;
                asm volatile("ldmatrix.sync.aligned.m8n8.x4.shared.b16 {%0,%1,%2,%3}, [%4];"
                             : "=r"(af[i][0]), "=r"(af[i][1]), "=r"(af[i][2]), "=r"(af[i][3])
                             : "r"(addr));
            }
            #pragma unroll
            for (int j = 0; j < 4; j++) {
                const uint32_t addr = bS + (uint32_t)((kb + b_row) * BSTR + b_col + j * 8) * 2;
                asm volatile("ldmatrix.sync.aligned.m8n8.x2.trans.shared.b16 {%0,%1}, [%2];"
                             : "=r"(bf[j][0]), "=r"(bf[j][1]) : "r"(addr));
            }
            #pragma unroll
            for (int i = 0; i < 4; i++)
                #pragma unroll
                for (int j = 0; j < 4; j++)
                    asm volatile(
                        "mma.sync.aligned.m16n8k16.row.col.f32.f16.f16.f32 "
                        "{%0,%1,%2,%3}, {%4,%5,%6,%7}, {%8,%9}, {%0,%1,%2,%3};"
                        : "+f"(acc[i][j][0]), "+f"(acc[i][j][1]),
                          "+f"(acc[i][j][2]), "+f"(acc[i][j][3])
                        : "r"(af[i][0]), "r"(af[i][1]), "r"(af[i][2]), "r"(af[i][3]),
                          "r"(bf[j][0]), "r"(bf[j][1]));
        }
    }

    const long zC = cZ * bz;
    const float* bsp = bias + (long)biasZ * bz;
    #pragma unroll
    for (int i = 0; i < 4; i++) {
        const int r0 = by * BM + wm * 64 + i * 16 + gid;
        #pragma unroll
        for (int j = 0; j < 4; j++) {
            const int cn = bx * BN + wn * 32 + j * 8 + tig * 2;
            const float b0 = bsp[cn], b1 = bsp[cn + 1];
            float v00 = acc[i][j][0] + b0, v01 = acc[i][j][1] + b1;
            float v10 = acc[i][j][2] + b0, v11 = acc[i][j][3] + b1;
            if (EPI == 2) {
                v00 += extra[(long)r0 * ldc + cn];
                v01 += extra[(long)r0 * ldc + cn + 1];
                v10 += extra[(long)(r0 + 8) * ldc + cn];
                v11 += extra[(long)(r0 + 8) * ldc + cn + 1];
            }
            if (EPI == 1) {
                __half* Ch = (__half*)C;
                *(uint32_t*)(Ch + zC + (long)r0 * ldc + cn) =
                    h2u(__floats2half2_rn(v00, v01));
                *(uint32_t*)(Ch + zC + (long)(r0 + 8) * ldc + cn) =
                    h2u(__floats2half2_rn(v10, v11));
            } else {
                float* Cf = (float*)C;
                float2 lo = { v00, v01 }, hi = { v10, v11 };
                *(float2*)(Cf + zC + (long)r0 * ldc + cn)       = lo;
                *(float2*)(Cf + zC + (long)(r0 + 8) * ldc + cn) = hi;
            }
        }
    }
}

// ---------------------------------------------------------------------------
// emb: ss[b,:] = silu(emb[b,:]) @ emb_W + emb_b
// ---------------------------------------------------------------------------
__global__ __launch_bounds__(256) void emb_kernel(
    const float* __restrict__ emb, const float* __restrict__ embW,
    const float* __restrict__ embb, float* __restrict__ ss)
{
    __shared__ float se[TED];
    const int b = blockIdx.y;
    const int j = blockIdx.x * 256 + threadIdx.x;
    for (int i = threadIdx.x; i < TED; i += 256)
        se[i] = silu_f(emb[b * TED + i]);
    __syncthreads();
    float acc = embb[j];
    #pragma unroll 8
    for (int k = 0; k < TED; k++)
        acc += se[k] * embW[(long)k * TED + j];
    ss[b * TED + j] = acc;
}

// ---------------------------------------------------------------------------
// per-token LayerNorm -> modulate -> SiLU -> fp16. 2 tokens per warp,
// fp16 y input (uint4 loads), params loaded once per token pair.
// ---------------------------------------------------------------------------
__global__ __launch_bounds__(256) void ln_mod_silu(
    const __half* __restrict__ y, const float* __restrict__ ss,
    const float* __restrict__ lnw, const float* __restrict__ lnb,
    __half* __restrict__ g)
{
    const int warp = threadIdx.x >> 5, lane = threadIdx.x & 31;
    const long t0 = ((long)blockIdx.x * 8 + warp) * 2;
    const __half* y0 = y + t0 * DD;
    const __half* y1 = y0 + DD;

    uint4 va[4], vb[4];
    #pragma unroll
    for (int i = 0; i < 4; i++) {
        va[i] = *(const uint4*)(y0 + i * 256 + lane * 8);
        vb[i] = *(const uint4*)(y1 + i * 256 + lane * 8);
    }

    float s0 = 0.f, q0 = 0.f, s1 = 0.f, q1 = 0.f;
    #pragma unroll
    for (int i = 0; i < 4; i++) {
        const uint32_t* wa = &va[i].x;
        const uint32_t* wb = &vb[i].x;
        #pragma unroll
        for (int w = 0; w < 4; w++) {
            float2 fa = __half22float2(u2h(wa[w]));
            float2 fb = __half22float2(u2h(wb[w]));
            s0 += fa.x + fa.y; q0 += fa.x * fa.x + fa.y * fa.y;
            s1 += fb.x + fb.y; q1 += fb.x * fb.x + fb.y * fb.y;
        }
    }
    #pragma unroll
    for (int o = 16; o; o >>= 1) {
        s0 += __shfl_xor_sync(0xffffffffu, s0, o);
        q0 += __shfl_xor_sync(0xffffffffu, q0, o);
        s1 += __shfl_xor_sync(0xffffffffu, s1, o);
        q1 += __shfl_xor_sync(0xffffffffu, q1, o);
    }
    const float m0 = s0 * (1.0f / DD);
    const float r0 = rsqrtf(q0 * (1.0f / DD) - m0 * m0 + 1e-5f);
    const float m1 = s1 * (1.0f / DD);
    const float r1 = rsqrtf(q1 * (1.0f / DD) - m1 * m1 + 1e-5f);

    const int b = (int)(t0 >> 12);           // pair never crosses a batch
    const float* scp = ss + b * TED;
    __half* g0 = g + t0 * DD;
    __half* g1 = g0 + DD;

    #pragma unroll
    for (int i = 0; i < 4; i++) {
        const int c = i * 256 + lane * 8;
        float4 w4a = *(const float4*)(lnw + c);
        float4 w4b = *(const float4*)(lnw + c + 4);
        float4 b4a = *(const float4*)(lnb + c);
        float4 b4b = *(const float4*)(lnb + c + 4);
        float4 sca = *(const float4*)(scp + c);
        float4 scb = *(const float4*)(scp + c + 4);
        float4 sha = *(const float4*)(scp + DD + c);
        float4 shb = *(const float4*)(scp + DD + c + 4);
        const float wv[8] = { w4a.x, w4a.y, w4a.z, w4a.w, w4b.x, w4b.y, w4b.z, w4b.w };
        const float bv[8] = { b4a.x, b4a.y, b4a.z, b4a.w, b4b.x, b4b.y, b4b.z, b4b.w };
        const float sv[8] = { sca.x, sca.y, sca.z, sca.w, scb.x, scb.y, scb.z, scb.w };
        const float hv[8] = { sha.x, sha.y, sha.z, sha.w, shb.x, shb.y, shb.z, shb.w };

        const uint32_t* wa = &va[i].x;
        const uint32_t* wb = &vb[i].x;
        uint4 oa, ob;
        uint32_t* oaw = &oa.x;
        uint32_t* obw = &ob.x;
        #pragma unroll
        for (int w = 0; w < 4; w++) {
            float2 fa = __half22float2(u2h(wa[w]));
            float2 fb = __half22float2(u2h(wb[w]));
            float h, p0, p1;
            h = (fa.x - m0) * r0 * wv[w * 2] + bv[w * 2];
            h = h * (1.f + sv[w * 2]) + hv[w * 2];           p0 = silu_f(h);
            h = (fa.y - m0) * r0 * wv[w * 2 + 1] + bv[w * 2 + 1];
            h = h * (1.f + sv[w * 2 + 1]) + hv[w * 2 + 1];   p1 = silu_f(h);
            oaw[w] = h2u(__floats2half2_rn(p0, p1));
            h = (fb.x - m1) * r1 * wv[w * 2] + bv[w * 2];
            h = h * (1.f + sv[w * 2]) + hv[w * 2];           p0 = silu_f(h);
            h = (fb.y - m1) * r1 * wv[w * 2 + 1] + bv[w * 2 + 1];
            h = h * (1.f + sv[w * 2 + 1]) + hv[w * 2 + 1];   p1 = silu_f(h);
            obw[w] = h2u(__floats2half2_rn(p0, p1));
        }
        *(uint4*)(g0 + c) = oa;
        *(uint4*)(g1 + c) = ob;
    }
}

// ---------------------------------------------------------------------------
extern "C" void kernel_launch(void* const* d_in, const int* in_sizes, int n_in,
                              void* d_out, int out_size)
{
    const float* x     = (const float*)d_in[0];
    const float* emb   = (const float*)d_in[1];
    const float* W1    = (const float*)d_in[2];
    const float* b1    = (const float*)d_in[3];
    const float* W2    = (const float*)d_in[4];
    const float* b2    = (const float*)d_in[5];
    const float* ln_w  = (const float*)d_in[6];
    const float* ln_b  = (const float*)d_in[7];
    const float* emb_W = (const float*)d_in[8];
    const float* emb_b = (const float*)d_in[9];
    const float* out_W = (const float*)d_in[10];
    const float* out_b = (const float*)d_in[11];
    float* out = (float*)d_out;

    float *ss;
    __half *h1, *yh, *gg, *w1h, *w2h, *owh;
    cudaGetSymbolAddress((void**)&ss, g_ss);
    cudaGetSymbolAddress((void**)&h1, g_h1);
    cudaGetSymbolAddress((void**)&yh, g_yh);
    cudaGetSymbolAddress((void**)&gg, g_g);
    cudaGetSymbolAddress((void**)&w1h, g_w1h);
    cudaGetSymbolAddress((void**)&w2h, g_w2h);
    cudaGetSymbolAddress((void**)&owh, g_owh);

    cudaFuncSetAttribute(reinterpret_cast<const void*>(&g1_gemm),
                         cudaFuncAttributeMaxDynamicSharedMemorySize, G1_SMEM);
    cudaFuncSetAttribute(reinterpret_cast<const void*>(&mma_gemm<1, __half>),
                         cudaFuncAttributeMaxDynamicSharedMemorySize, SMEM_BYTES);
    cudaFuncSetAttribute(reinterpret_cast<const void*>(&mma_gemm<2, float>),
                         cudaFuncAttributeMaxDynamicSharedMemorySize, SMEM_BYTES);

    // 0) convert weights to fp16
    {
        long blocks = (N4_W + 255) / 256;
        to_half_w<<<(int)blocks, 256>>>(
            (const float4*)W1, (uint2*)w1h,
            (const float4*)W2, (uint2*)w2h,
            (const float4*)out_W, (uint2*)owh);
    }

    // 1) scale/shift
    emb_kernel<<<dim3(8, 4), 256>>>(emb, emb_W, emb_b, ss);

    // 2) h1 = half(gelu(x_head @ W1 + b1))
    g1_gemm<<<dim3(128, 8), 256, G1_SMEM>>>(x, w1h, h1, b1);

    // 3) y = half(h1 @ W2 + b2): per head M=16384, N=128, K=512
    mma_gemm<1, __half><<<dim3(1, 128, 8), 256, SMEM_BYTES>>>(
        h1, FFND, HH * FFND,
        w2h, (long)FFND * LDIM, LDIM,
        yh, LDIM, DD,
        b2, LDIM, nullptr, FFND);

    // 4) g = half(silu(modulated LN(y))), 2 tokens/warp
    ln_mod_silu<<<TOK / 16, 256>>>(yh, ss, ln_w, ln_b, gg);

    // 5) out = x + g @ out_W + out_b: M=16384, N=1024, K=1024
    mma_gemm<2, float><<<dim3(8, 128, 1), 256, SMEM_BYTES>>>(
        gg, 0, DD,
        owh, 0, DD,
        out, 0, DD,
        out_b, 0, x, DD);
}